// round 9
// baseline (speedup 1.0000x reference)
#include <cuda_runtime.h>

// Problem constants
#define S    8192
#define D    768
#define D4   (D/4)        // 192 float4 per row
#define NA   256
#define NO   256
#define NSP  (NA+NO)      // 512 spans
#define NP   (NA*NO)      // 65536 pairs
#define NCAT 13
#define NPOL 3
#define NK   18           // 2 valid + 13 cat + 3 pol partials per span
#define RPG  8            // rows per pool stage-1 group
#define NG   5            // groups per span (MAXW=40 -> 5*8)
#define TI   8            // aspect tile
#define TJ   8            // opinion tile

// Output layout (flattened tuple, fp32)
#define OFF_AID ((size_t)NP * (2*D))
#define OFF_OID (OFF_AID + NP)
#define OFF_CAT (OFF_OID + NP)
#define OFF_POL (OFF_CAT + (size_t)NP*NCAT)
#define OFF_MSK (OFF_POL + (size_t)NP*NPOL)

// Scratch (allocation-free rule: device globals)
__device__ float g_tmp[NSP * NG * D];  // per-(span,group) partial maxima
__device__ float g_rep[NSP * D];       // aspect rows [0,256), opinion rows [256,512)
__device__ float g_part[NSP * NK];     // per-span partial logits (18 each)

static __device__ __forceinline__ void vmax(float4& a, const float4 b) {
    a.x = fmaxf(a.x, b.x);
    a.y = fmaxf(a.y, b.y);
    a.z = fmaxf(a.z, b.z);
    a.w = fmaxf(a.w, b.w);
}

// ---------------------------------------------------------------------------
// Pool stage 1: grid (NG, NSP). Block (g, s) max-pools up to RPG rows of
// span s into g_tmp[s][g]. Empty groups exit immediately.
// ---------------------------------------------------------------------------
__global__ void __launch_bounds__(192) pool_stage1(
    const float* __restrict__ word_rep,
    const int*   __restrict__ aspects,
    const int*   __restrict__ opinions)
{
    int g = blockIdx.x;
    int s = blockIdx.y;
    const int* sp = (s < NA) ? (aspects + 2*s) : (opinions + 2*(s - NA));
    int head = sp[0];
    int w    = sp[1] - head;                  // 1..40
    int r0 = g * RPG;
    if (r0 >= w) return;
    int n = min(RPG, w - r0);

    int c = threadIdx.x;
    const float4* base = (const float4*)word_rep + (size_t)(head + r0) * D4 + c;

    float4 m0 = base[0];
    float4 m1 = m0;
    int k = 1;
    for (; k + 1 < n; k += 2) {
        float4 a0 = base[(size_t)(k+0) * D4];
        float4 a1 = base[(size_t)(k+1) * D4];
        vmax(m0, a0); vmax(m1, a1);
    }
    if (k < n) vmax(m0, base[(size_t)k * D4]);
    vmax(m0, m1);
    ((float4*)g_tmp)[(size_t)(s * NG + g) * D4 + c] = m0;
}

// ---------------------------------------------------------------------------
// Pool stage 2: reduce group maxima -> g_rep (exact max, fixed order).
// ---------------------------------------------------------------------------
__global__ void __launch_bounds__(192) pool_stage2(
    const int* __restrict__ aspects,
    const int* __restrict__ opinions)
{
    int s = blockIdx.x;
    const int* sp = (s < NA) ? (aspects + 2*s) : (opinions + 2*(s - NA));
    int w  = sp[1] - sp[0];
    int ng = (w + RPG - 1) / RPG;

    int c = threadIdx.x;
    const float4* t = ((const float4*)g_tmp) + (size_t)(s * NG) * D4 + c;
    float4 m = t[0];
    for (int g = 1; g < ng; ++g)
        vmax(m, t[(size_t)g * D4]);
    ((float4*)g_rep)[(size_t)s * D4 + c] = m;
}

// ---------------------------------------------------------------------------
// Per-span partial logits (deterministic order; unchanged math).
// ---------------------------------------------------------------------------
__global__ void __launch_bounds__(192) part_kernel(
    const float* __restrict__ Wv,
    const float* __restrict__ Wc,
    const float* __restrict__ Wp)
{
    int s = blockIdx.x;
    int rowoff = (s < NA) ? 0 : D;
    int tid = threadIdx.x;

    float4 r = ((const float4*)g_rep)[(size_t)s * D4 + tid];
    int d = rowoff + tid * 4;

    float acc[NK];
    #pragma unroll
    for (int c = 0; c < 2; ++c)
        acc[c] = r.x*Wv[(d+0)*2+c] + r.y*Wv[(d+1)*2+c]
               + r.z*Wv[(d+2)*2+c] + r.w*Wv[(d+3)*2+c];
    #pragma unroll
    for (int c = 0; c < NCAT; ++c)
        acc[2+c] = r.x*Wc[(d+0)*NCAT+c] + r.y*Wc[(d+1)*NCAT+c]
                 + r.z*Wc[(d+2)*NCAT+c] + r.w*Wc[(d+3)*NCAT+c];
    #pragma unroll
    for (int c = 0; c < NPOL; ++c)
        acc[15+c] = r.x*Wp[(d+0)*NPOL+c] + r.y*Wp[(d+1)*NPOL+c]
                  + r.z*Wp[(d+2)*NPOL+c] + r.w*Wp[(d+3)*NPOL+c];

    #pragma unroll
    for (int k = 0; k < NK; ++k)
        #pragma unroll
        for (int off = 16; off > 0; off >>= 1)
            acc[k] += __shfl_xor_sync(0xFFFFFFFFu, acc[k], off);

    __shared__ float sred[6][NK];
    int warp = tid >> 5;
    if ((tid & 31) == 0) {
        #pragma unroll
        for (int k = 0; k < NK; ++k) sred[warp][k] = acc[k];
    }
    __syncthreads();
    if (tid < NK) {
        float t = 0.f;
        #pragma unroll
        for (int w = 0; w < 6; ++w) t += sred[w][tid];   // fixed order
        g_part[s * NK + tid] = t;
    }
}

// ---------------------------------------------------------------------------
// Tiled pair kernel. One block = TI x TJ = 64 pairs, 384 threads.
// Writes 64 x 6KB = 384KB per block but reads only 16 rep rows (48KB),
// served from L1 with 8x reuse -> L2 read traffic drops ~8x, leaving the
// LTS/DRAM budget to the 403MB store stream. Warp-uniform source split:
// warps 0-5 (c<192) stream the aspect half, warps 6-11 the opinion half.
// Also emits ids/cat/pol/mask (folded tail).
// ---------------------------------------------------------------------------
__global__ void __launch_bounds__(384) pair_tile_kernel(
    const float* __restrict__ bv,
    const float* __restrict__ bc,
    const float* __restrict__ bp,
    float* __restrict__ out)
{
    int j0 = blockIdx.x * TJ;          // opinion tile (fast dimension)
    int i0 = blockIdx.y * TI;          // aspect tile
    int tid = threadIdx.x;             // 0..383

    __shared__ float smask[TI * TJ];

    // Phase 1: masks for the 64 pairs (same g_part reads/order as before).
    if (tid < TI * TJ) {
        int ii = tid >> 3, jj = tid & 7;
        const float* pa = g_part + (i0 + ii) * NK;
        const float* po = g_part + (NA + j0 + jj) * NK;
        float v0 = pa[0] + po[0] + bv[0];
        float v1 = pa[1] + po[1] + bv[1];
        smask[tid] = (v0 > v1) ? 1.f : 0.f;
    }
    __syncthreads();

    // Phase 2: small outputs. thread (q = tid&63, r = tid>>6) writes items
    // {r, r+6, r+12} (and r==0 also item 18) of the 19-item tail per pair.
    {
        int q = tid & 63, r = tid >> 6;        // r in 0..5
        int ii = q >> 3, jj = q & 7;
        int i = i0 + ii, j = j0 + jj;
        size_t p = (size_t)i * NO + j;
        float m = smask[q];
        bool mb = m != 0.f;
        const float* pa = g_part + i * NK;
        const float* po = g_part + (NA + j) * NK;
        #pragma unroll
        for (int u = 0; u < 3; ++u) {
            int k = r + 6 * u;                 // 0..17
            if (k < NCAT) {
                out[OFF_CAT + p * NCAT + k] = mb ? (pa[2+k] + po[2+k] + bc[k]) : 0.f;
            } else if (k < 16) {
                int kk = k - NCAT;             // 0..2
                out[OFF_POL + p * NPOL + kk] = mb ? (pa[15+kk] + po[15+kk] + bp[kk]) : 0.f;
            } else if (k == 16) {
                out[OFF_AID + p] = mb ? (float)i : -1.f;
            } else { // k == 17
                out[OFF_OID + p] = mb ? (float)j : -1.f;
            }
        }
        if (r == 0) out[OFF_MSK + p] = m;      // item 18
    }

    // Phase 3: the big stream. c<192 -> aspect half, c>=192 -> opinion half.
    int c = tid;                                // float4 column 0..383
    bool isA = c < D4;                          // warp-uniform
    const float4* repA = ((const float4*)g_rep) + (size_t)i0 * D4 + c;          // +ii*D4
    const float4* repO = ((const float4*)g_rep) + (size_t)(NA + j0) * D4 + (c - D4); // +jj*D4
    float4* ob = ((float4*)out) + ((size_t)i0 * NO + j0) * (2 * D4) + c;

    float4 v;
    #pragma unroll
    for (int ii = 0; ii < TI; ++ii) {
        if (isA) v = __ldg(repA + (size_t)ii * D4);
        float4* orow = ob + (size_t)ii * NO * (2 * D4);
        #pragma unroll
        for (int jj = 0; jj < TJ; ++jj) {
            if (!isA) v = __ldg(repO + (size_t)jj * D4);
            float m = smask[(ii << 3) | jj];
            float4 wv = make_float4(v.x * m, v.y * m, v.z * m, v.w * m);
            __stcs(orow + (size_t)jj * (2 * D4), wv);
        }
    }
}

// ---------------------------------------------------------------------------
extern "C" void kernel_launch(void* const* d_in, const int* in_sizes, int n_in,
                              void* d_out, int out_size)
{
    const float* word_rep = (const float*)d_in[0];   // (S, D)
    const int*   aspects  = (const int*)  d_in[1];   // (NA, 2)
    const int*   opinions = (const int*)  d_in[2];   // (NO, 2)
    const float* W_valid  = (const float*)d_in[3];   // (2D, 2)
    const float* b_valid  = (const float*)d_in[4];   // (2,)
    const float* W_cat    = (const float*)d_in[5];   // (2D, 13)
    const float* b_cat    = (const float*)d_in[6];   // (13,)
    const float* W_pol    = (const float*)d_in[7];   // (2D, 3)
    const float* b_pol    = (const float*)d_in[8];   // (3,)
    float* out = (float*)d_out;

    dim3 g1(NG, NSP);
    pool_stage1<<<g1, 192>>>(word_rep, aspects, opinions);
    pool_stage2<<<NSP, 192>>>(aspects, opinions);
    part_kernel<<<NSP, 192>>>(W_valid, W_cat, W_pol);
    dim3 gp(NO / TJ, NA / TI);                       // 32 x 32 tiles
    pair_tile_kernel<<<gp, 384>>>(b_valid, b_cat, b_pol, out);
}

// round 12
// speedup vs baseline: 1.1271x; 1.1271x over previous
#include <cuda_runtime.h>

// Problem constants
#define S    8192
#define D    768
#define D4   (D/4)        // 192 float4 per row
#define NA   256
#define NO   256
#define NSP  (NA+NO)      // 512 spans
#define NP   (NA*NO)      // 65536 pairs
#define NCAT 13
#define NPOL 3
#define NK   18           // 2 valid + 13 cat + 3 pol partials per span
#define TJ   16           // opinion tile (pairs per block, same aspect)

// Output layout (flattened tuple, fp32)
#define OFF_AID ((size_t)NP * (2*D))
#define OFF_OID (OFF_AID + NP)
#define OFF_CAT (OFF_OID + NP)
#define OFF_POL (OFF_CAT + (size_t)NP*NCAT)
#define OFF_MSK (OFF_POL + (size_t)NP*NPOL)

// Scratch (allocation-free rule: device globals)
__device__ float g_rep[NSP * D];       // aspect rows [0,256), opinion rows [256,512)
__device__ float g_part[NSP * NK];     // per-span partial logits (18 each)

static __device__ __forceinline__ void vmax(float4& a, const float4 b) {
    a.x = fmaxf(a.x, b.x);
    a.y = fmaxf(a.y, b.y);
    a.z = fmaxf(a.z, b.z);
    a.w = fmaxf(a.w, b.w);
}

// ---------------------------------------------------------------------------
// Kernel A: span max-pool, EXACT R1 version (best measured: 10.8us).
// One block per span, 192 threads = 1 float4 lane each, serial row loop.
// ---------------------------------------------------------------------------
__global__ void __launch_bounds__(192) span_pool_kernel(
    const float* __restrict__ word_rep,
    const int*   __restrict__ aspects,
    const int*   __restrict__ opinions)
{
    int s = blockIdx.x;                       // 0..511
    const int* sp = (s < NA) ? (aspects + 2*s) : (opinions + 2*(s - NA));
    int head = sp[0];
    int w    = sp[1] - head;                  // 1..40
    int c = threadIdx.x;                      // float4 lane 0..191

    const float4* wr = (const float4*)word_rep;
    float4 m = wr[(size_t)head * D4 + c];
    for (int k = 1; k < w; ++k)
        vmax(m, wr[(size_t)(head + k) * D4 + c]);
    ((float4*)g_rep)[(size_t)s * D4 + c] = m;
}

// ---------------------------------------------------------------------------
// Kernel B: per-span partial logits (identical to R1 — deterministic order).
// ---------------------------------------------------------------------------
__global__ void __launch_bounds__(192) part_kernel(
    const float* __restrict__ Wv,   // (2D, 2)   row-major
    const float* __restrict__ Wc,   // (2D, 13)
    const float* __restrict__ Wp)   // (2D, 3)
{
    int s = blockIdx.x;                       // 0..511
    int rowoff = (s < NA) ? 0 : D;
    int tid = threadIdx.x;                    // 0..191

    float4 r = ((const float4*)g_rep)[(size_t)s * D4 + tid];
    int d = rowoff + tid * 4;

    float acc[NK];
    #pragma unroll
    for (int c = 0; c < 2; ++c)
        acc[c] = r.x*Wv[(d+0)*2+c] + r.y*Wv[(d+1)*2+c]
               + r.z*Wv[(d+2)*2+c] + r.w*Wv[(d+3)*2+c];
    #pragma unroll
    for (int c = 0; c < NCAT; ++c)
        acc[2+c] = r.x*Wc[(d+0)*NCAT+c] + r.y*Wc[(d+1)*NCAT+c]
                 + r.z*Wc[(d+2)*NCAT+c] + r.w*Wc[(d+3)*NCAT+c];
    #pragma unroll
    for (int c = 0; c < NPOL; ++c)
        acc[15+c] = r.x*Wp[(d+0)*NPOL+c] + r.y*Wp[(d+1)*NPOL+c]
                  + r.z*Wp[(d+2)*NPOL+c] + r.w*Wp[(d+3)*NPOL+c];

    #pragma unroll
    for (int k = 0; k < NK; ++k)
        #pragma unroll
        for (int off = 16; off > 0; off >>= 1)
            acc[k] += __shfl_xor_sync(0xFFFFFFFFu, acc[k], off);

    __shared__ float sred[6][NK];
    int warp = tid >> 5;
    if ((tid & 31) == 0) {
        #pragma unroll
        for (int k = 0; k < NK; ++k) sred[warp][k] = acc[k];
    }
    __syncthreads();
    if (tid < NK) {
        float t = 0.f;
        #pragma unroll
        for (int w = 0; w < 6; ++w) t += sred[w][tid];   // fixed order
        g_part[s * NK + tid] = t;
    }
}

// ---------------------------------------------------------------------------
// Kernel C: 1x16 tiled pair kernel. One block = pairs (i, j0..j0+15):
// 16 CONTIGUOUS output rows (96KB contiguous write per block, blocks in
// order -> compact DRAM write front, same locality as the R1 kernel), while
// the aspect row is loaded once and reused 16x -> L2 read traffic drops
// 403MB -> ~215MB, relieving the LTS cap. Warp-uniform source split:
// warps 0-5 (c<192) hold the aspect half, warps 6-11 load opinion rows.
// Tails (ids/cat/pol/mask) folded in: one item per thread (304 of 384).
// ---------------------------------------------------------------------------
__global__ void __launch_bounds__(384) pair_kernel(
    const float* __restrict__ bv,
    const float* __restrict__ bc,
    const float* __restrict__ bp,
    float* __restrict__ out)
{
    int p0 = blockIdx.x * TJ;          // first pair of tile
    int i  = p0 >> 8;                  // aspect id (fixed: TJ divides 256)
    int j0 = p0 & 255;                 // first opinion id
    int tid = threadIdx.x;             // 0..383

    __shared__ float smask[TJ];

    // Phase 1: masks (same g_part reads/order as before -> bit-identical).
    if (tid < TJ) {
        const float* pa = g_part + i * NK;
        const float* po = g_part + (NA + j0 + tid) * NK;
        float v0 = pa[0] + po[0] + bv[0];
        float v1 = pa[1] + po[1] + bv[1];
        smask[tid] = (v0 > v1) ? 1.f : 0.f;
    }
    __syncthreads();

    // Phase 2: small outputs — one of 19 items per pair per thread.
    if (tid < TJ * 19) {
        int pr = tid / 19;             // pair within tile 0..15
        int k  = tid - pr * 19;        // item 0..18
        int j = j0 + pr;
        size_t p = (size_t)p0 + pr;
        float m = smask[pr];
        bool mb = m != 0.f;
        const float* pa = g_part + i * NK;
        const float* po = g_part + (NA + j) * NK;
        if (k < NCAT) {
            out[OFF_CAT + p * NCAT + k] = mb ? (pa[2+k] + po[2+k] + bc[k]) : 0.f;
        } else if (k < 16) {
            int kk = k - NCAT;
            out[OFF_POL + p * NPOL + kk] = mb ? (pa[15+kk] + po[15+kk] + bp[kk]) : 0.f;
        } else if (k == 16) {
            out[OFF_AID + p] = mb ? (float)i : -1.f;
        } else if (k == 17) {
            out[OFF_OID + p] = mb ? (float)j : -1.f;
        } else {
            out[OFF_MSK + p] = m;
        }
    }

    // Phase 3: the big stream. 96KB contiguous per block.
    int c = tid;                        // float4 column 0..383
    bool isA = c < D4;                  // warp-uniform
    const float4* repO = ((const float4*)g_rep) + (size_t)(NA + j0) * D4 + (c - D4);
    float4 av;
    if (isA) av = __ldg(((const float4*)g_rep) + (size_t)i * D4 + c);
    float4* ob = ((float4*)out) + (size_t)p0 * (2 * D4) + c;

    #pragma unroll
    for (int jj = 0; jj < TJ; ++jj) {
        float4 v = av;
        if (!isA) v = __ldg(repO + (size_t)jj * D4);
        float m = smask[jj];
        float4 wv = make_float4(v.x * m, v.y * m, v.z * m, v.w * m);
        __stcs(ob + (size_t)jj * (2 * D4), wv);
    }
}

// ---------------------------------------------------------------------------
extern "C" void kernel_launch(void* const* d_in, const int* in_sizes, int n_in,
                              void* d_out, int out_size)
{
    const float* word_rep = (const float*)d_in[0];   // (S, D)
    const int*   aspects  = (const int*)  d_in[1];   // (NA, 2)
    const int*   opinions = (const int*)  d_in[2];   // (NO, 2)
    const float* W_valid  = (const float*)d_in[3];   // (2D, 2)
    const float* b_valid  = (const float*)d_in[4];   // (2,)
    const float* W_cat    = (const float*)d_in[5];   // (2D, 13)
    const float* b_cat    = (const float*)d_in[6];   // (13,)
    const float* W_pol    = (const float*)d_in[7];   // (2D, 3)
    const float* b_pol    = (const float*)d_in[8];   // (3,)
    float* out = (float*)d_out;

    span_pool_kernel<<<NSP, 192>>>(word_rep, aspects, opinions);
    part_kernel     <<<NSP, 192>>>(W_valid, W_cat, W_pol);
    pair_kernel     <<<NP / TJ, 384>>>(b_valid, b_cat, b_pol, out);
}

// round 14
// speedup vs baseline: 1.1367x; 1.0084x over previous
#include <cuda_runtime.h>

// Problem constants
#define S    8192
#define D    768
#define D4   (D/4)        // 192 float4 per row
#define NA   256
#define NO   256
#define NSP  (NA+NO)      // 512 spans
#define NP   (NA*NO)      // 65536 pairs
#define NCAT 13
#define NPOL 3
#define NK   18           // 2 valid + 13 cat + 3 pol partials per span
#define BATCH 8           // unconditional load batch (MLP=8)

// Output layout (flattened tuple, fp32)
#define OFF_AID ((size_t)NP * (2*D))
#define OFF_OID (OFF_AID + NP)
#define OFF_CAT (OFF_OID + NP)
#define OFF_POL (OFF_CAT + (size_t)NP*NCAT)
#define OFF_MSK (OFF_POL + (size_t)NP*NPOL)

// Scratch (allocation-free rule: device globals)
__device__ float g_rep[NSP * D];       // aspect rows [0,256), opinion rows [256,512)
__device__ float g_part[NSP * NK];     // per-span partial logits (18 each)

static __device__ __forceinline__ void vmax(float4& a, const float4 b) {
    a.x = fmaxf(a.x, b.x);
    a.y = fmaxf(a.y, b.y);
    a.z = fmaxf(a.z, b.z);
    a.w = fmaxf(a.w, b.w);
}

// ---------------------------------------------------------------------------
// Kernel A: span max-pool with UNCONDITIONAL batched loads.
// head ranges over [0, S-MAXW), so head+k is in-bounds for ALL k < 40
// independent of w -> we may load 8 rows back-to-back with no guard
// (8 outstanding LDG.128 per thread), then fold in only the valid ones via
// predicated fmaxf. Critical path for the w=40 tail block falls from
// 40 serial load-latencies to 5 batch-latencies. Max is exactly
// associative/commutative -> bit-identical result.
// ---------------------------------------------------------------------------
__global__ void __launch_bounds__(192) span_pool_kernel(
    const float* __restrict__ word_rep,
    const int*   __restrict__ aspects,
    const int*   __restrict__ opinions)
{
    int s = blockIdx.x;                       // 0..511
    const int* sp = (s < NA) ? (aspects + 2*s) : (opinions + 2*(s - NA));
    int head = sp[0];
    int w    = sp[1] - head;                  // 1..40
    int c = threadIdx.x;                      // float4 lane 0..191

    const float4* base = (const float4*)word_rep + (size_t)head * D4 + c;

    float4 m = base[0];                       // k = 0 always valid
    for (int kb = 1; kb < w; kb += BATCH) {
        float4 a[BATCH];
        #pragma unroll
        for (int u = 0; u < BATCH; ++u)       // unconditional, always in-bounds
            a[u] = base[(size_t)(kb + u) * D4];
        #pragma unroll
        for (int u = 0; u < BATCH; ++u)       // predicated merge
            if (kb + u < w) vmax(m, a[u]);
    }
    ((float4*)g_rep)[(size_t)s * D4 + c] = m;
}

// ---------------------------------------------------------------------------
// Kernel B: per-span partial logits (identical to R1 — deterministic order).
// ---------------------------------------------------------------------------
__global__ void __launch_bounds__(192) part_kernel(
    const float* __restrict__ Wv,   // (2D, 2)   row-major
    const float* __restrict__ Wc,   // (2D, 13)
    const float* __restrict__ Wp)   // (2D, 3)
{
    int s = blockIdx.x;                       // 0..511
    int rowoff = (s < NA) ? 0 : D;
    int tid = threadIdx.x;                    // 0..191

    float4 r = ((const float4*)g_rep)[(size_t)s * D4 + tid];
    int d = rowoff + tid * 4;

    float acc[NK];
    #pragma unroll
    for (int c = 0; c < 2; ++c)
        acc[c] = r.x*Wv[(d+0)*2+c] + r.y*Wv[(d+1)*2+c]
               + r.z*Wv[(d+2)*2+c] + r.w*Wv[(d+3)*2+c];
    #pragma unroll
    for (int c = 0; c < NCAT; ++c)
        acc[2+c] = r.x*Wc[(d+0)*NCAT+c] + r.y*Wc[(d+1)*NCAT+c]
                 + r.z*Wc[(d+2)*NCAT+c] + r.w*Wc[(d+3)*NCAT+c];
    #pragma unroll
    for (int c = 0; c < NPOL; ++c)
        acc[15+c] = r.x*Wp[(d+0)*NPOL+c] + r.y*Wp[(d+1)*NPOL+c]
                  + r.z*Wp[(d+2)*NPOL+c] + r.w*Wp[(d+3)*NPOL+c];

    #pragma unroll
    for (int k = 0; k < NK; ++k)
        #pragma unroll
        for (int off = 16; off > 0; off >>= 1)
            acc[k] += __shfl_xor_sync(0xFFFFFFFFu, acc[k], off);

    __shared__ float sred[6][NK];
    int warp = tid >> 5;
    if ((tid & 31) == 0) {
        #pragma unroll
        for (int k = 0; k < NK; ++k) sred[warp][k] = acc[k];
    }
    __syncthreads();
    if (tid < NK) {
        float t = 0.f;
        #pragma unroll
        for (int w = 0; w < 6; ++w) t += sred[w][tid];   // fixed order
        g_part[s * NK + tid] = t;
    }
}

// ---------------------------------------------------------------------------
// Kernel C: EXACT R1 pair kernel (best measured in-graph: ~63.5us).
// One block per pair, 128 threads, contiguous 6KB write per block,
// __stcs streaming stores.
// ---------------------------------------------------------------------------
__global__ void __launch_bounds__(128) pair_kernel(
    const float* __restrict__ bv,
    const float* __restrict__ bc,
    const float* __restrict__ bp,
    float* __restrict__ out)
{
    int p = blockIdx.x;
    int i = p >> 8;            // aspect id
    int j = p & 255;           // opinion id

    const float* pa = g_part + i * NK;
    const float* po = g_part + (NA + j) * NK;

    float v0 = pa[0] + po[0] + bv[0];
    float v1 = pa[1] + po[1] + bv[1];
    bool m = v0 > v1;

    int t = threadIdx.x;
    const float4* ar = ((const float4*)g_rep) + (size_t)i        * D4;
    const float4* op = ((const float4*)g_rep) + (size_t)(NA + j) * D4;
    float4* outp = ((float4*)out) + (size_t)p * (2 * D4);

    const float4 z4 = make_float4(0.f, 0.f, 0.f, 0.f);
    #pragma unroll
    for (int it = 0; it < 3; ++it) {
        int c = t + it * 128;                // 0..383
        float4 v = z4;
        if (m) v = (c < D4) ? ar[c] : op[c - D4];
        __stcs(&outp[c], v);
    }

    if (t < NCAT)
        out[OFF_CAT + (size_t)p * NCAT + t] = m ? (pa[2 + t] + po[2 + t] + bc[t]) : 0.f;
    if (t >= 32 && t < 32 + NPOL) {
        int k = t - 32;
        out[OFF_POL + (size_t)p * NPOL + k] = m ? (pa[15 + k] + po[15 + k] + bp[k]) : 0.f;
    }
    if (t == 64) {
        out[OFF_AID + p] = m ? (float)i : -1.f;
        out[OFF_OID + p] = m ? (float)j : -1.f;
        out[OFF_MSK + p] = m ? 1.f : 0.f;
    }
}

// ---------------------------------------------------------------------------
extern "C" void kernel_launch(void* const* d_in, const int* in_sizes, int n_in,
                              void* d_out, int out_size)
{
    const float* word_rep = (const float*)d_in[0];   // (S, D)
    const int*   aspects  = (const int*)  d_in[1];   // (NA, 2)
    const int*   opinions = (const int*)  d_in[2];   // (NO, 2)
    const float* W_valid  = (const float*)d_in[3];   // (2D, 2)
    const float* b_valid  = (const float*)d_in[4];   // (2,)
    const float* W_cat    = (const float*)d_in[5];   // (2D, 13)
    const float* b_cat    = (const float*)d_in[6];   // (13,)
    const float* W_pol    = (const float*)d_in[7];   // (2D, 3)
    const float* b_pol    = (const float*)d_in[8];   // (3,)
    float* out = (float*)d_out;

    span_pool_kernel<<<NSP, 192>>>(word_rep, aspects, opinions);
    part_kernel     <<<NSP, 192>>>(W_valid, W_cat, W_pol);
    pair_kernel     <<<NP, 128>>>(b_valid, b_cat, b_pol, out);
}